// round 15
// baseline (speedup 1.0000x reference)
#include <cuda_runtime.h>

// softmax(f[n]+g[m]) over m cancels f[n] -> all output rows identical.
// Single fused kernel, 64 CTAs x 544 thr (17 warps):
//   stage A: 128 thr/CTA reduce 128 rows (4 warps shuffle-reduce) -> 17-float partial
//   barrier: TICKET barrier; LAST arriver skips the poll (it's on the critical path)
//   stage B: 17 warps reduce partials, 128 thr compute row, 512 thr store 4MB
//            with adjacent float4 pairs (256-bit STG fusable).

#define NB 64
#define NT 544          // 17 warps: stage B1 needs one warp per column
#define D_IN 16
#define DH   18

__device__ float g_part[17 * NB];            // [col][block]
__device__ unsigned int g_arrive = 0;        // monotonic ticket counter (2^32 % 64 == 0)

__device__ __forceinline__ unsigned int atom_add_release_gpu(unsigned int* p) {
    unsigned int old;
    asm volatile("atom.add.release.gpu.global.u32 %0, [%1], 1;"
                 : "=r"(old) : "l"(p) : "memory");
    return old;
}
__device__ __forceinline__ unsigned int ld_acquire_gpu(const unsigned int* p) {
    unsigned int v;
    asm volatile("ld.acquire.gpu.global.u32 %0, [%1];" : "=r"(v) : "l"(p) : "memory");
    return v;
}

__global__ void __launch_bounds__(NT, 1) fused_kernel(
    const float* __restrict__ x,
    const float* __restrict__ W,
    const float* __restrict__ a,
    const float* __restrict__ Wk,
    float* __restrict__ out)
{
    __shared__ float wa2[16];
    __shared__ float wsum[4][17];
    __shared__ float red[17];
    __shared__ float orow[128];
    int tid  = threadIdx.x;
    int warp = tid >> 5, lane = tid & 31;
    int bid  = blockIdx.x;

    // ---- prologue: all independent loads issued first ----
    float4 x0, x1, x2, x3;
    if (tid < 128) {
        const float4* xr = reinterpret_cast<const float4*>(
            x + (size_t)(bid * 128 + tid) * D_IN);
        x0 = xr[0]; x1 = xr[1]; x2 = xr[2]; x3 = xr[3];
    }
    if (tid >= 128 && tid < 144) {      // warp 4: wa2 = W @ a2
        int r = tid - 128;
        float s = 0.f;
        #pragma unroll
        for (int j = 0; j < DH; ++j) s += W[r * DH + j] * a[DH + j];
        wa2[r] = s;
    }
    float wcol[16];                      // Wk column, in regs across the barrier
    if (tid < 128) {
        int h = tid >> 4, d = tid & 15;
        const float* Wh = Wk + h * (D_IN * D_IN);
        #pragma unroll
        for (int k = 0; k < 16; ++k) wcol[k] = Wh[k * 16 + d];
    }
    __syncthreads();

    // ---- stage A: exp-weighted reduce of this CTA's 128 rows ----
    if (tid < 128) {
        float xv[16] = { x0.x, x0.y, x0.z, x0.w,  x1.x, x1.y, x1.z, x1.w,
                         x2.x, x2.y, x2.z, x2.w,  x3.x, x3.y, x3.z, x3.w };
        // shallow tree for g = <xv, wa2>
        float t0 = xv[0]*wa2[0]   + xv[1]*wa2[1];
        float t1 = xv[2]*wa2[2]   + xv[3]*wa2[3];
        float t2 = xv[4]*wa2[4]   + xv[5]*wa2[5];
        float t3 = xv[6]*wa2[6]   + xv[7]*wa2[7];
        float t4 = xv[8]*wa2[8]   + xv[9]*wa2[9];
        float t5 = xv[10]*wa2[10] + xv[11]*wa2[11];
        float t6 = xv[12]*wa2[12] + xv[13]*wa2[13];
        float t7 = xv[14]*wa2[14] + xv[15]*wa2[15];
        float g = ((t0+t1)+(t2+t3)) + ((t4+t5)+(t6+t7));
        float e = __expf(g);             // |g| <~ 3; fast-path exp, err ~2^-21

        float p[17];
        #pragma unroll
        for (int k = 0; k < 16; ++k) p[k] = e * xv[k];
        p[16] = e;

        #pragma unroll
        for (int off = 16; off > 0; off >>= 1) {
            #pragma unroll
            for (int i = 0; i < 17; ++i)
                p[i] += __shfl_down_sync(0xffffffffu, p[i], off);
        }
        if (lane == 0) {
            #pragma unroll
            for (int i = 0; i < 17; ++i) wsum[warp][i] = p[i];
        }
    }
    __syncthreads();

    if (tid < 17)
        g_part[tid * NB + bid] =
            wsum[0][tid] + wsum[1][tid] + wsum[2][tid] + wsum[3][tid];
    __syncthreads();   // partial stores happen-before tid0's release-arrive

    // ---- ticket barrier: last arriver skips the poll entirely ----
    if (tid == 0) {
        unsigned int old = atom_add_release_gpu(&g_arrive);
        unsigned int target = (old / NB + 1u) * NB;   // end of this round
        if (old + 1u != target) {
            while (ld_acquire_gpu(&g_arrive) < target) { }
        }
    }
    __syncthreads();

    // ---- stage B1: warp w (<17) reduces global column w: 64 floats ----
    if (warp < 17) {
        const float* col = g_part + warp * NB;
        float v = col[lane] + col[lane + 32];
        #pragma unroll
        for (int off = 16; off > 0; off >>= 1)
            v += __shfl_down_sync(0xffffffffu, v, off);
        if (lane == 0) red[warp] = v;
    }
    __syncthreads();

    // ---- stage B2: out_row[h*16+d] = (nvec @ Wk[h]) / Z ----
    if (tid < 128) {
        float invZ = 1.0f / red[16];
        float s = 0.f;
        #pragma unroll
        for (int k = 0; k < 16; ++k) s += red[k] * wcol[k];
        orow[tid] = s * invZ;
    }
    __syncthreads();

    // ---- stage B3: broadcast 128 rows; each thread stores 8 consecutive
    //      floats per row (adjacent float4 pair -> 256-bit STG fusable) ----
    if (tid < 512) {
        int c8 = tid & 15;               // 8-float chunk 0..15 within a row
        int r0 = tid >> 4;               // 0..31
        float4 v0 = make_float4(orow[c8*8+0], orow[c8*8+1], orow[c8*8+2], orow[c8*8+3]);
        float4 v1 = make_float4(orow[c8*8+4], orow[c8*8+5], orow[c8*8+6], orow[c8*8+7]);
        float4* o4 = reinterpret_cast<float4*>(out);
        size_t base = (size_t)(bid * 128) * 32;
        #pragma unroll
        for (int i = 0; i < 4; ++i) {
            size_t rowoff = base + (size_t)(r0 + i * 32) * 32 + c8 * 2;
            o4[rowoff]     = v0;
            o4[rowoff + 1] = v1;
        }
    }
    // no tail: kernel ends at last store
}

extern "C" void kernel_launch(void* const* d_in, const int* in_sizes, int n_in,
                              void* d_out, int out_size) {
    const float* x  = (const float*)d_in[0];  // (8192,16)
    const float* W  = (const float*)d_in[1];  // (16,18)
    const float* a  = (const float*)d_in[2];  // (36,1)
    const float* Wk = (const float*)d_in[3];  // (8,16,16)
    float* out = (float*)d_out;               // (8192,128)

    fused_kernel<<<NB, NT>>>(x, W, a, Wk, out);
}

// round 16
// speedup vs baseline: 1.2177x; 1.2177x over previous
#include <cuda_runtime.h>

// softmax(f[n]+g[m]) over m cancels f[n] -> all output rows identical.
// Single fused kernel, 64 CTAs x 544 thr (17 warps) — R13 structure +
// __expf + tree-dot + last-arriver poll skip. Stores: R13 coalesced layout.

#define NB 64
#define NT 544          // 17 warps: stage B1 needs one warp per column
#define D_IN 16
#define DH   18

__device__ float g_part[17 * NB];            // [col][block]
__device__ unsigned int g_arrive = 0;        // monotonic ticket counter (2^32 % 64 == 0)

__device__ __forceinline__ unsigned int atom_add_release_gpu(unsigned int* p) {
    unsigned int old;
    asm volatile("atom.add.release.gpu.global.u32 %0, [%1], 1;"
                 : "=r"(old) : "l"(p) : "memory");
    return old;
}
__device__ __forceinline__ unsigned int ld_acquire_gpu(const unsigned int* p) {
    unsigned int v;
    asm volatile("ld.acquire.gpu.global.u32 %0, [%1];" : "=r"(v) : "l"(p) : "memory");
    return v;
}

__global__ void __launch_bounds__(NT, 1) fused_kernel(
    const float* __restrict__ x,
    const float* __restrict__ W,
    const float* __restrict__ a,
    const float* __restrict__ Wk,
    float* __restrict__ out)
{
    __shared__ float wa2[16];
    __shared__ float wsum[4][17];
    __shared__ float red[17];
    __shared__ float orow[128];
    int tid  = threadIdx.x;
    int warp = tid >> 5, lane = tid & 31;
    int bid  = blockIdx.x;

    // ---- prologue: all independent loads issued first ----
    float4 x0, x1, x2, x3;
    if (tid < 128) {
        const float4* xr = reinterpret_cast<const float4*>(
            x + (size_t)(bid * 128 + tid) * D_IN);
        x0 = xr[0]; x1 = xr[1]; x2 = xr[2]; x3 = xr[3];
    }
    if (tid >= 128 && tid < 144) {      // warp 4: wa2 = W @ a2
        int r = tid - 128;
        float s = 0.f;
        #pragma unroll
        for (int j = 0; j < DH; ++j) s += W[r * DH + j] * a[DH + j];
        wa2[r] = s;
    }
    float wcol[16];                      // Wk column, in regs across the barrier
    if (tid < 128) {
        int h = tid >> 4, d = tid & 15;
        const float* Wh = Wk + h * (D_IN * D_IN);
        #pragma unroll
        for (int k = 0; k < 16; ++k) wcol[k] = Wh[k * 16 + d];
    }
    __syncthreads();

    // ---- stage A: exp-weighted reduce of this CTA's 128 rows ----
    if (tid < 128) {
        float xv[16] = { x0.x, x0.y, x0.z, x0.w,  x1.x, x1.y, x1.z, x1.w,
                         x2.x, x2.y, x2.z, x2.w,  x3.x, x3.y, x3.z, x3.w };
        // shallow tree for g = <xv, wa2>
        float t0 = xv[0]*wa2[0]   + xv[1]*wa2[1];
        float t1 = xv[2]*wa2[2]   + xv[3]*wa2[3];
        float t2 = xv[4]*wa2[4]   + xv[5]*wa2[5];
        float t3 = xv[6]*wa2[6]   + xv[7]*wa2[7];
        float t4 = xv[8]*wa2[8]   + xv[9]*wa2[9];
        float t5 = xv[10]*wa2[10] + xv[11]*wa2[11];
        float t6 = xv[12]*wa2[12] + xv[13]*wa2[13];
        float t7 = xv[14]*wa2[14] + xv[15]*wa2[15];
        float g = ((t0+t1)+(t2+t3)) + ((t4+t5)+(t6+t7));
        float e = __expf(g);             // |g| <~ 3; MUFU fast path, err ~2^-21

        float p[17];
        #pragma unroll
        for (int k = 0; k < 16; ++k) p[k] = e * xv[k];
        p[16] = e;

        #pragma unroll
        for (int off = 16; off > 0; off >>= 1) {
            #pragma unroll
            for (int i = 0; i < 17; ++i)
                p[i] += __shfl_down_sync(0xffffffffu, p[i], off);
        }
        if (lane == 0) {
            #pragma unroll
            for (int i = 0; i < 17; ++i) wsum[warp][i] = p[i];
        }
    }
    __syncthreads();

    if (tid < 17)
        g_part[tid * NB + bid] =
            wsum[0][tid] + wsum[1][tid] + wsum[2][tid] + wsum[3][tid];
    __syncthreads();   // partial stores happen-before tid0's release-arrive

    // ---- ticket barrier: last arriver skips the poll ----
    if (tid == 0) {
        unsigned int old = atom_add_release_gpu(&g_arrive);
        unsigned int target = (old / NB + 1u) * NB;   // end of this round
        if (old + 1u != target) {
            while (ld_acquire_gpu(&g_arrive) < target) { }
        }
    }
    __syncthreads();

    // ---- stage B1: warp w (<17) reduces global column w: 64 floats ----
    if (warp < 17) {
        const float* col = g_part + warp * NB;
        float v = col[lane] + col[lane + 32];
        #pragma unroll
        for (int off = 16; off > 0; off >>= 1)
            v += __shfl_down_sync(0xffffffffu, v, off);
        if (lane == 0) red[warp] = v;
    }
    __syncthreads();

    // ---- stage B2: out_row[h*16+d] = (nvec @ Wk[h]) / Z ----
    if (tid < 128) {
        float invZ = 1.0f / red[16];
        float s = 0.f;
        #pragma unroll
        for (int k = 0; k < 16; ++k) s += red[k] * wcol[k];
        orow[tid] = s * invZ;
    }
    __syncthreads();

    // ---- stage B3 (R13 layout): 128 rows = 4096 float4; 512 thr x 8 stores,
    //      warp-coalesced: lanes cover 32 consecutive float4 of one row ----
    if (tid < 512) {
        int c4 = tid & 31;               // float4 column 0..31
        int r0 = tid >> 5;               // 0..15
        float4 val = make_float4(orow[c4 * 4 + 0], orow[c4 * 4 + 1],
                                 orow[c4 * 4 + 2], orow[c4 * 4 + 3]);
        float4* o4 = reinterpret_cast<float4*>(out);
        size_t base = (size_t)(bid * 128) * 32;
        #pragma unroll
        for (int i = 0; i < 8; ++i)
            o4[base + (size_t)(r0 + i * 16) * 32 + c4] = val;
    }
    // no tail: kernel ends at last store
}

extern "C" void kernel_launch(void* const* d_in, const int* in_sizes, int n_in,
                              void* d_out, int out_size) {
    const float* x  = (const float*)d_in[0];  // (8192,16)
    const float* W  = (const float*)d_in[1];  // (16,18)
    const float* a  = (const float*)d_in[2];  // (36,1)
    const float* Wk = (const float*)d_in[3];  // (8,16,16)
    float* out = (float*)d_out;               // (8192,128)

    fused_kernel<<<NB, NT>>>(x, W, a, Wk, out);
}